// round 7
// baseline (speedup 1.0000x reference)
#include <cuda_runtime.h>
#include <cuda_fp16.h>

#define N_NODES 50000
#define N_EDGES 800000
#define EMB     100
#define EPSN    1e-12f
#define FULL    0xffffffffu

// Scratch (allocation-free rule: __device__ globals)
__device__ __half g_embH[N_NODES * EMB];
__device__ __half g_bufHA[N_NODES * EMB];
__device__ __half g_bufHB[N_NODES * EMB];
__device__ int    g_deg[N_NODES];
__device__ int    g_rank[N_EDGES];
__device__ int    g_rowptr[N_NODES];
__device__ int    g_counter;
__device__ int2   g_cells[N_EDGES];       // {col, val-as-int-bits}

// ---------------------------------------------------------------------------
// Prep: embH = fp16(emb); zero deg/counter. One warp per row.
// (No out write — the final layer's fused epilogue produces out in one pass.)
// ---------------------------------------------------------------------------
__global__ void __launch_bounds__(256)
prep_kernel(const float* __restrict__ emb, __half* __restrict__ embh,
            int* __restrict__ deg, int* __restrict__ counter)
{
    int t = blockIdx.x * blockDim.x + threadIdx.x;
    if (t < N_NODES) deg[t] = 0;
    if (t == 0) *counter = 0;

    int warp = t >> 5;
    int lane = t & 31;
    if (warp >= N_NODES || lane >= 25) return;

    float4 v = __ldg((const float4*)(emb + (size_t)warp * EMB) + lane);
    __half2 h0 = __floats2half2_rn(v.x, v.y);
    __half2 h1 = __floats2half2_rn(v.z, v.w);
    uint2 u;
    u.x = *(unsigned*)&h0; u.y = *(unsigned*)&h1;
    ((uint2*)(embh + (size_t)warp * EMB))[lane] = u;
}

// ---------------------------------------------------------------------------
// CSR build: histogram recording each edge's rank within its row, then
// warp-aggregated atomic offsets, then atomic-free scatter (1 edge/thread).
// ---------------------------------------------------------------------------
__global__ void hist_rank_kernel(const int* __restrict__ rows,
                                 int* __restrict__ deg, int* __restrict__ rank)
{
    int e = blockIdx.x * blockDim.x + threadIdx.x;
    if (e < N_EDGES) rank[e] = atomicAdd(&deg[rows[e]], 1);
}

__global__ void offsets_kernel(const int* __restrict__ deg, int* __restrict__ rowptr,
                               int* __restrict__ counter)
{
    int i = blockIdx.x * blockDim.x + threadIdx.x;
    int lane = threadIdx.x & 31;
    int d = (i < N_NODES) ? deg[i] : 0;

    int s = d;                                   // warp inclusive scan
#pragma unroll
    for (int o = 1; o < 32; o <<= 1) {
        int t = __shfl_up_sync(FULL, s, o);
        if (lane >= o) s += t;
    }
    int total = __shfl_sync(FULL, s, 31);
    int base = 0;
    if (lane == 31) base = atomicAdd(counter, total);
    base = __shfl_sync(FULL, base, 31);
    if (i < N_NODES) rowptr[i] = base + s - d;   // exclusive within warp
}

__global__ void scatter_kernel(const int* __restrict__ rows,
                               const int* __restrict__ cols,
                               const float* __restrict__ vals,
                               const int* __restrict__ rowptr,
                               const int* __restrict__ rank,
                               int2* __restrict__ cells)
{
    int e = blockIdx.x * blockDim.x + threadIdx.x;
    if (e >= N_EDGES) return;
    int r = __ldg(rows + e);
    int pos = __ldg(rowptr + r) + __ldg(rank + e);
    cells[pos] = make_int2(__ldg(cols + e), __float_as_int(__ldg(vals + e)));
}

// ---------------------------------------------------------------------------
// SpMM body (warp per row, unroll x2 — the measured-best variant): returns
// the fp32 accumulator for this warp's destination row (4 dims per lane).
// ---------------------------------------------------------------------------
__device__ __forceinline__ float4
spmm_row(const int* __restrict__ rowptr, const int* __restrict__ deg,
         const int2* __restrict__ cells, const __half* __restrict__ xh,
         int warp, int lane, bool act)
{
    int p   = __ldg(rowptr + warp);
    int end = p + __ldg(deg + warp);

    float4 acc = make_float4(0.f, 0.f, 0.f, 0.f);

    for (; p + 1 < end; p += 2) {
        int2 cv0 = __ldg(cells + p);
        int2 cv1 = __ldg(cells + p + 1);
        if (act) {
            uint2 u0 = __ldg((const uint2*)(xh + (size_t)cv0.x * EMB) + lane);
            uint2 u1 = __ldg((const uint2*)(xh + (size_t)cv1.x * EMB) + lane);
            float w0 = __int_as_float(cv0.y);
            float w1 = __int_as_float(cv1.y);
            float2 p0 = __half22float2(*(__half2*)&u0.x);
            float2 q0 = __half22float2(*(__half2*)&u0.y);
            float2 p1 = __half22float2(*(__half2*)&u1.x);
            float2 q1 = __half22float2(*(__half2*)&u1.y);
            acc.x += w0 * p0.x; acc.y += w0 * p0.y;
            acc.z += w0 * q0.x; acc.w += w0 * q0.y;
            acc.x += w1 * p1.x; acc.y += w1 * p1.y;
            acc.z += w1 * q1.x; acc.w += w1 * q1.y;
        }
    }
    if (p < end) {
        int2 cv = __ldg(cells + p);
        if (act) {
            uint2 u = __ldg((const uint2*)(xh + (size_t)cv.x * EMB) + lane);
            float w = __int_as_float(cv.y);
            float2 pp = __half22float2(*(__half2*)&u.x);
            float2 qq = __half22float2(*(__half2*)&u.y);
            acc.x += w * pp.x; acc.y += w * pp.y;
            acc.z += w * qq.x; acc.w += w * qq.y;
        }
    }
    return acc;
}

__device__ __forceinline__ float warp_norm_scale(float4 v, float a)
{
    float ss = v.x * v.x + v.y * v.y + v.z * v.z + v.w * v.w;
#pragma unroll
    for (int o = 16; o; o >>= 1) ss += __shfl_xor_sync(FULL, ss, o);
    return a / fmaxf(sqrtf(ss), EPSN);
}

// ---------------------------------------------------------------------------
// Layers 1 & 2: pure gather -> fp16 write. No out traffic, no reduction.
// ---------------------------------------------------------------------------
__global__ void __launch_bounds__(256)
spmm_mid_kernel(const int* __restrict__ rowptr, const int* __restrict__ deg,
                const int2* __restrict__ cells, const __half* __restrict__ xh,
                __half* __restrict__ yh)
{
    int warp = (blockIdx.x * blockDim.x + threadIdx.x) >> 5;
    int lane = threadIdx.x & 31;
    if (warp >= N_NODES) return;
    bool act = lane < 25;

    float4 acc = spmm_row(rowptr, deg, cells, xh, warp, lane, act);

    if (act) {
        __half2 h0 = __floats2half2_rn(acc.x, acc.y);
        __half2 h1 = __floats2half2_rn(acc.z, acc.w);
        uint2 u;
        u.x = *(unsigned*)&h0; u.y = *(unsigned*)&h1;
        ((uint2*)(yh + (size_t)warp * EMB))[lane] = u;
    }
}

// ---------------------------------------------------------------------------
// Layer 3 + fused final combine: gather layer-3 row, then load the same
// destination row from emb (fp32), bufA, bufB (fp16, row-aligned coalesced),
// compute all 4 norms in-warp, and write out once:
//   out = a0*n(emb) + a1*n(x1) + a2*n(x2) + a3*n(x3)
// ---------------------------------------------------------------------------
__global__ void __launch_bounds__(256)
spmm_final_kernel(const int* __restrict__ rowptr, const int* __restrict__ deg,
                  const int2* __restrict__ cells, const __half* __restrict__ xh,
                  const float* __restrict__ emb, const __half* __restrict__ x1h,
                  const __half* __restrict__ x2h, float* __restrict__ out,
                  const float* __restrict__ a)
{
    int warp = (blockIdx.x * blockDim.x + threadIdx.x) >> 5;
    int lane = threadIdx.x & 31;
    if (warp >= N_NODES) return;
    bool act = lane < 25;

    float4 acc = spmm_row(rowptr, deg, cells, xh, warp, lane, act);

    float4 e  = make_float4(0.f, 0.f, 0.f, 0.f);
    float4 v1 = make_float4(0.f, 0.f, 0.f, 0.f);
    float4 v2 = make_float4(0.f, 0.f, 0.f, 0.f);
    if (act) {
        e = __ldg((const float4*)(emb + (size_t)warp * EMB) + lane);
        uint2 u1 = __ldg((const uint2*)(x1h + (size_t)warp * EMB) + lane);
        uint2 u2 = __ldg((const uint2*)(x2h + (size_t)warp * EMB) + lane);
        float2 a1 = __half22float2(*(__half2*)&u1.x);
        float2 b1 = __half22float2(*(__half2*)&u1.y);
        float2 a2 = __half22float2(*(__half2*)&u2.x);
        float2 b2 = __half22float2(*(__half2*)&u2.y);
        v1 = make_float4(a1.x, a1.y, b1.x, b1.y);
        v2 = make_float4(a2.x, a2.y, b2.x, b2.y);
    }

    float s0 = warp_norm_scale(e,   __ldg(a + 0));
    float s1 = warp_norm_scale(v1,  __ldg(a + 1));
    float s2 = warp_norm_scale(v2,  __ldg(a + 2));
    float s3 = warp_norm_scale(acc, __ldg(a + 3));

    if (act) {
        float4 o;
        o.x = s0 * e.x + s1 * v1.x + s2 * v2.x + s3 * acc.x;
        o.y = s0 * e.y + s1 * v1.y + s2 * v2.y + s3 * acc.y;
        o.z = s0 * e.z + s1 * v1.z + s2 * v2.z + s3 * acc.z;
        o.w = s0 * e.w + s1 * v1.w + s2 * v2.w + s3 * acc.w;
        ((float4*)(out + (size_t)warp * EMB))[lane] = o;
    }
}

// ---------------------------------------------------------------------------
// Launch: inputs are adj_row, adj_col, adj_val, embedding, a
// ---------------------------------------------------------------------------
extern "C" void kernel_launch(void* const* d_in, const int* in_sizes, int n_in,
                              void* d_out, int out_size)
{
    const int*   adj_row = (const int*)  d_in[0];
    const int*   adj_col = (const int*)  d_in[1];
    const float* adj_val = (const float*)d_in[2];
    const float* emb     = (const float*)d_in[3];
    const float* a       = (const float*)d_in[4];
    float*       out     = (float*)d_out;

    __half* embh; cudaGetSymbolAddress((void**)&embh, g_embH);
    __half* bufA; cudaGetSymbolAddress((void**)&bufA, g_bufHA);
    __half* bufB; cudaGetSymbolAddress((void**)&bufB, g_bufHB);
    int*   deg;   cudaGetSymbolAddress((void**)&deg,   g_deg);
    int*   rank;  cudaGetSymbolAddress((void**)&rank,  g_rank);
    int*   rp;    cudaGetSymbolAddress((void**)&rp,    g_rowptr);
    int*   cnt;   cudaGetSymbolAddress((void**)&cnt,   g_counter);
    int2*  cells; cudaGetSymbolAddress((void**)&cells, g_cells);

    const int EB   = (N_EDGES + 255) / 256;
    const int ROWB = (N_NODES * 32 + 255) / 256;
    const int NODB = (N_NODES + 255) / 256;

    // prep + CSR build (rank trick: no atomics in scatter)
    prep_kernel<<<ROWB, 256>>>(emb, embh, deg, cnt);
    hist_rank_kernel<<<EB, 256>>>(adj_row, deg, rank);
    offsets_kernel<<<NODB, 256>>>(deg, rp, cnt);
    scatter_kernel<<<EB, 256>>>(adj_row, adj_col, adj_val, rp, rank, cells);
    // layers 1-2: pure gather; layer 3: fused normalize-and-combine epilogue
    spmm_mid_kernel  <<<ROWB, 256>>>(rp, deg, cells, embh, bufA);
    spmm_mid_kernel  <<<ROWB, 256>>>(rp, deg, cells, bufA, bufB);
    spmm_final_kernel<<<ROWB, 256>>>(rp, deg, cells, bufB, emb, bufA, bufB, out, a);
}

// round 8
// speedup vs baseline: 1.5625x; 1.5625x over previous
#include <cuda_runtime.h>
#include <cuda_fp16.h>

#define N_NODES 50000
#define N_EDGES 800000
#define EMB     100
#define EPSN    1e-12f
#define FULL    0xffffffffu

// Scratch (allocation-free rule: __device__ globals)
__device__ __half g_embH[N_NODES * EMB];
__device__ __half g_bufHA[N_NODES * EMB];
__device__ __half g_bufHB[N_NODES * EMB];
__device__ int    g_deg[N_NODES];
__device__ int    g_rank[N_EDGES];
__device__ int    g_rowptr[N_NODES];
__device__ int    g_counter;
__device__ int2   g_cells[N_EDGES];       // {col, val-as-int-bits}

// ---------------------------------------------------------------------------
// Prep: embH = fp16(emb); zero deg/counter. One warp per row.
// ---------------------------------------------------------------------------
__global__ void __launch_bounds__(256)
prep_kernel(const float* __restrict__ emb, __half* __restrict__ embh,
            int* __restrict__ deg, int* __restrict__ counter)
{
    int t = blockIdx.x * blockDim.x + threadIdx.x;
    if (t < N_NODES) deg[t] = 0;
    if (t == 0) *counter = 0;

    int warp = t >> 5;
    int lane = t & 31;
    if (warp >= N_NODES || lane >= 25) return;

    float4 v = __ldg((const float4*)(emb + (size_t)warp * EMB) + lane);
    __half2 h0 = __floats2half2_rn(v.x, v.y);
    __half2 h1 = __floats2half2_rn(v.z, v.w);
    uint2 u;
    u.x = *(unsigned*)&h0; u.y = *(unsigned*)&h1;
    ((uint2*)(embh + (size_t)warp * EMB))[lane] = u;
}

// ---------------------------------------------------------------------------
// CSR build: histogram recording each edge's rank within its row, then
// warp-aggregated atomic offsets, then atomic-free scatter (1 edge/thread).
// ---------------------------------------------------------------------------
__global__ void hist_rank_kernel(const int* __restrict__ rows,
                                 int* __restrict__ deg, int* __restrict__ rank)
{
    int e = blockIdx.x * blockDim.x + threadIdx.x;
    if (e < N_EDGES) rank[e] = atomicAdd(&deg[rows[e]], 1);
}

__global__ void offsets_kernel(const int* __restrict__ deg, int* __restrict__ rowptr,
                               int* __restrict__ counter)
{
    int i = blockIdx.x * blockDim.x + threadIdx.x;
    int lane = threadIdx.x & 31;
    int d = (i < N_NODES) ? deg[i] : 0;

    int s = d;                                   // warp inclusive scan
#pragma unroll
    for (int o = 1; o < 32; o <<= 1) {
        int t = __shfl_up_sync(FULL, s, o);
        if (lane >= o) s += t;
    }
    int total = __shfl_sync(FULL, s, 31);
    int base = 0;
    if (lane == 31) base = atomicAdd(counter, total);
    base = __shfl_sync(FULL, base, 31);
    if (i < N_NODES) rowptr[i] = base + s - d;   // exclusive within warp
}

__global__ void scatter_kernel(const int* __restrict__ rows,
                               const int* __restrict__ cols,
                               const float* __restrict__ vals,
                               const int* __restrict__ rowptr,
                               const int* __restrict__ rank,
                               int2* __restrict__ cells)
{
    int e = blockIdx.x * blockDim.x + threadIdx.x;
    if (e >= N_EDGES) return;
    // issue all independent loads before the dependent rowptr gather
    int   c  = __ldg(cols + e);
    float v  = __ldg(vals + e);
    int   rk = __ldg(rank + e);
    int   r  = __ldg(rows + e);
    int pos = __ldg(rowptr + r) + rk;
    cells[pos] = make_int2(c, __float_as_int(v));
}

// ---------------------------------------------------------------------------
// SpMM body (warp per row, unroll x2 — the measured-best variant): returns
// the fp32 accumulator for this warp's destination row (4 dims per lane).
// ---------------------------------------------------------------------------
__device__ __forceinline__ float4
spmm_row(const int* __restrict__ rowptr, const int* __restrict__ deg,
         const int2* __restrict__ cells, const __half* __restrict__ xh,
         int warp, int lane, bool act)
{
    int p   = __ldg(rowptr + warp);
    int end = p + __ldg(deg + warp);

    float4 acc = make_float4(0.f, 0.f, 0.f, 0.f);

    for (; p + 1 < end; p += 2) {
        int2 cv0 = __ldg(cells + p);
        int2 cv1 = __ldg(cells + p + 1);
        if (act) {
            uint2 u0 = __ldg((const uint2*)(xh + (size_t)cv0.x * EMB) + lane);
            uint2 u1 = __ldg((const uint2*)(xh + (size_t)cv1.x * EMB) + lane);
            float w0 = __int_as_float(cv0.y);
            float w1 = __int_as_float(cv1.y);
            float2 p0 = __half22float2(*(__half2*)&u0.x);
            float2 q0 = __half22float2(*(__half2*)&u0.y);
            float2 p1 = __half22float2(*(__half2*)&u1.x);
            float2 q1 = __half22float2(*(__half2*)&u1.y);
            acc.x += w0 * p0.x; acc.y += w0 * p0.y;
            acc.z += w0 * q0.x; acc.w += w0 * q0.y;
            acc.x += w1 * p1.x; acc.y += w1 * p1.y;
            acc.z += w1 * q1.x; acc.w += w1 * q1.y;
        }
    }
    if (p < end) {
        int2 cv = __ldg(cells + p);
        if (act) {
            uint2 u = __ldg((const uint2*)(xh + (size_t)cv.x * EMB) + lane);
            float w = __int_as_float(cv.y);
            float2 pp = __half22float2(*(__half2*)&u.x);
            float2 qq = __half22float2(*(__half2*)&u.y);
            acc.x += w * pp.x; acc.y += w * pp.y;
            acc.z += w * qq.x; acc.w += w * qq.y;
        }
    }
    return acc;
}

__device__ __forceinline__ float warp_norm_scale(float4 v, float a)
{
    float ss = v.x * v.x + v.y * v.y + v.z * v.z + v.w * v.w;
#pragma unroll
    for (int o = 16; o; o >>= 1) ss += __shfl_xor_sync(FULL, ss, o);
    return a / fmaxf(sqrtf(ss), EPSN);
}

// ---------------------------------------------------------------------------
// Layers 1 & 2: pure gather -> fp16 write. No out traffic, no reduction.
// ---------------------------------------------------------------------------
__global__ void __launch_bounds__(256)
spmm_mid_kernel(const int* __restrict__ rowptr, const int* __restrict__ deg,
                const int2* __restrict__ cells, const __half* __restrict__ xh,
                __half* __restrict__ yh)
{
    int warp = (blockIdx.x * blockDim.x + threadIdx.x) >> 5;
    int lane = threadIdx.x & 31;
    if (warp >= N_NODES) return;
    bool act = lane < 25;

    float4 acc = spmm_row(rowptr, deg, cells, xh, warp, lane, act);

    if (act) {
        __half2 h0 = __floats2half2_rn(acc.x, acc.y);
        __half2 h1 = __floats2half2_rn(acc.z, acc.w);
        uint2 u;
        u.x = *(unsigned*)&h0; u.y = *(unsigned*)&h1;
        ((uint2*)(yh + (size_t)warp * EMB))[lane] = u;
    }
}

// ---------------------------------------------------------------------------
// Layer 3 + fused final combine: gather layer-3 row, then load the same
// destination row from emb (fp32), bufA, bufB (fp16, row-aligned coalesced),
// compute all 4 norms in-warp, and write out once:
//   out = a0*n(emb) + a1*n(x1) + a2*n(x2) + a3*n(x3)
// ---------------------------------------------------------------------------
__global__ void __launch_bounds__(256)
spmm_final_kernel(const int* __restrict__ rowptr, const int* __restrict__ deg,
                  const int2* __restrict__ cells, const __half* __restrict__ xh,
                  const float* __restrict__ emb, const __half* __restrict__ x1h,
                  const __half* __restrict__ x2h, float* __restrict__ out,
                  const float* __restrict__ a)
{
    int warp = (blockIdx.x * blockDim.x + threadIdx.x) >> 5;
    int lane = threadIdx.x & 31;
    if (warp >= N_NODES) return;
    bool act = lane < 25;

    float4 acc = spmm_row(rowptr, deg, cells, xh, warp, lane, act);

    float4 e  = make_float4(0.f, 0.f, 0.f, 0.f);
    float4 v1 = make_float4(0.f, 0.f, 0.f, 0.f);
    float4 v2 = make_float4(0.f, 0.f, 0.f, 0.f);
    if (act) {
        e = __ldg((const float4*)(emb + (size_t)warp * EMB) + lane);
        uint2 u1 = __ldg((const uint2*)(x1h + (size_t)warp * EMB) + lane);
        uint2 u2 = __ldg((const uint2*)(x2h + (size_t)warp * EMB) + lane);
        float2 a1 = __half22float2(*(__half2*)&u1.x);
        float2 b1 = __half22float2(*(__half2*)&u1.y);
        float2 a2 = __half22float2(*(__half2*)&u2.x);
        float2 b2 = __half22float2(*(__half2*)&u2.y);
        v1 = make_float4(a1.x, a1.y, b1.x, b1.y);
        v2 = make_float4(a2.x, a2.y, b2.x, b2.y);
    }

    float s0 = warp_norm_scale(e,   __ldg(a + 0));
    float s1 = warp_norm_scale(v1,  __ldg(a + 1));
    float s2 = warp_norm_scale(v2,  __ldg(a + 2));
    float s3 = warp_norm_scale(acc, __ldg(a + 3));

    if (act) {
        float4 o;
        o.x = s0 * e.x + s1 * v1.x + s2 * v2.x + s3 * acc.x;
        o.y = s0 * e.y + s1 * v1.y + s2 * v2.y + s3 * acc.y;
        o.z = s0 * e.z + s1 * v1.z + s2 * v2.z + s3 * acc.z;
        o.w = s0 * e.w + s1 * v1.w + s2 * v2.w + s3 * acc.w;
        ((float4*)(out + (size_t)warp * EMB))[lane] = o;
    }
}

// ---------------------------------------------------------------------------
// Launch: inputs are adj_row, adj_col, adj_val, embedding, a
// ---------------------------------------------------------------------------
extern "C" void kernel_launch(void* const* d_in, const int* in_sizes, int n_in,
                              void* d_out, int out_size)
{
    const int*   adj_row = (const int*)  d_in[0];
    const int*   adj_col = (const int*)  d_in[1];
    const float* adj_val = (const float*)d_in[2];
    const float* emb     = (const float*)d_in[3];
    const float* a       = (const float*)d_in[4];
    float*       out     = (float*)d_out;

    __half* embh; cudaGetSymbolAddress((void**)&embh, g_embH);
    __half* bufA; cudaGetSymbolAddress((void**)&bufA, g_bufHA);
    __half* bufB; cudaGetSymbolAddress((void**)&bufB, g_bufHB);
    int*   deg;   cudaGetSymbolAddress((void**)&deg,   g_deg);
    int*   rank;  cudaGetSymbolAddress((void**)&rank,  g_rank);
    int*   rp;    cudaGetSymbolAddress((void**)&rp,    g_rowptr);
    int*   cnt;   cudaGetSymbolAddress((void**)&cnt,   g_counter);
    int2*  cells; cudaGetSymbolAddress((void**)&cells, g_cells);

    const int EB   = (N_EDGES + 255) / 256;
    const int ROWB = (N_NODES * 32 + 255) / 256;
    const int NODB = (N_NODES + 255) / 256;

    // prep + CSR build (rank trick: no atomics in scatter)
    prep_kernel<<<ROWB, 256>>>(emb, embh, deg, cnt);
    hist_rank_kernel<<<EB, 256>>>(adj_row, deg, rank);
    offsets_kernel<<<NODB, 256>>>(deg, rp, cnt);
    scatter_kernel<<<EB, 256>>>(adj_row, adj_col, adj_val, rp, rank, cells);
    // layers 1-2: pure gather; layer 3: fused normalize-and-combine epilogue
    spmm_mid_kernel  <<<ROWB, 256>>>(rp, deg, cells, embh, bufA);
    spmm_mid_kernel  <<<ROWB, 256>>>(rp, deg, cells, bufA, bufB);
    spmm_final_kernel<<<ROWB, 256>>>(rp, deg, cells, bufB, emb, bufA, bufB, out, a);
}